// round 10
// baseline (speedup 1.0000x reference)
#include <cuda_runtime.h>
#include <cuda_bf16.h>
#include <cstdint>
#include <cstddef>

static constexpr int B_  = 4;
static constexpr int N_  = 4096;
static constexpr int F_  = 256;
static constexpr int FO_ = 64;
static constexpr int TM_ = 128;    // t rows per CTA

// ---- main smem map ----
// adj: 2 buf x 128 rows x 528B = 135168  @ 0   (epilogue: reused as 3x32KB C-merge)
// V:   2 buf x 32KB (hi16K+lo16K)        @ 135168
// EB:  2 buf x (EB1 512B + EB2 512B)     @ 200704
// sden [4][128] floats                   @ 202752
static constexpr int ADJSTRIDE = 528;
static constexpr int ADJBUF = 128 * ADJSTRIDE;   // 67584
static constexpr int VOFF = 2 * ADJBUF;          // 135168
static constexpr int VBUF = 32768;
static constexpr int EBO  = VOFF + 2 * VBUF;     // 200704
static constexpr int SDEN = EBO + 2048;          // 202752
static constexpr int SMEM_MAIN = SDEN + 2048;    // 204800

// k2 smem: ctx chunk [32][66] + Ws chunk [64][64]
static constexpr int K2_CS_STRIDE = 66;
static constexpr int K2_WS_OFF = 32 * K2_CS_STRIDE * 4;   // 8448
static constexpr int K2_SMEM  = K2_WS_OFF + 64 * 64 * 4;  // 24832

__device__ float g_EA1[B_ * N_];
__device__ float g_EA2[B_ * N_];
__device__ float g_EB1[B_ * N_];
__device__ float g_EB2[B_ * N_];
__device__ __nv_bfloat16 g_Vhi[(size_t)B_ * N_ * FO_];
__device__ __nv_bfloat16 g_Vlo[(size_t)B_ * N_ * FO_];

__device__ __forceinline__ uint32_t smem_u32(const void* p) {
    uint32_t a;
    asm("{ .reg .u64 t; cvta.to.shared.u64 t, %1; cvt.u32.u64 %0, t; }" : "=r"(a) : "l"(p));
    return a;
}
__device__ __forceinline__ uint32_t pack_hi(float a, float b) {
    uint32_t r;
    asm("prmt.b32 %0, %1, %2, 0x7632;" : "=r"(r)
        : "r"(__float_as_uint(a)), "r"(__float_as_uint(b)));
    return r;
}
__device__ __forceinline__ uint32_t pack_rn(float a, float b) {
    uint32_t r;
    asm("cvt.rn.bf16x2.f32 %0, %1, %2;" : "=r"(r) : "f"(b), "f"(a));
    return r;
}
__device__ __forceinline__ float trunc_bf16(float a) {
    return __uint_as_float(__float_as_uint(a) & 0xFFFF0000u);
}
__device__ __forceinline__ void ldsm4t(uint32_t* r, uint32_t addr) {
    asm volatile("ldmatrix.sync.aligned.m8n8.x4.trans.shared.b16 {%0,%1,%2,%3}, [%4];"
        : "=r"(r[0]), "=r"(r[1]), "=r"(r[2]), "=r"(r[3]) : "r"(addr));
}
__device__ __forceinline__ void mma16816(float* c, uint32_t a0, uint32_t a1, uint32_t a2, uint32_t a3,
                                         uint32_t b0, uint32_t b1) {
    asm volatile("mma.sync.aligned.m16n8k16.row.col.f32.bf16.bf16.f32 "
        "{%0,%1,%2,%3}, {%4,%5,%6,%7}, {%8,%9}, {%0,%1,%2,%3};"
        : "+f"(c[0]), "+f"(c[1]), "+f"(c[2]), "+f"(c[3])
        : "r"(a0), "r"(a1), "r"(a2), "r"(a3), "r"(b0), "r"(b1));
}
__device__ __forceinline__ void cp16(uint32_t dst, const void* src) {
    asm volatile("cp.async.cg.shared.global [%0], [%1], 16;" :: "r"(dst), "l"(src) : "memory");
}
__device__ __forceinline__ void cp_commit() { asm volatile("cp.async.commit_group;" ::: "memory"); }
template <int NW>
__device__ __forceinline__ void cp_wait() { asm volatile("cp.async.wait_group %0;" :: "n"(NW) : "memory"); }

// ---------------- K2: V (hi/lo) + EA   (grid 512, 32 rows/block) ----------------
__global__ __launch_bounds__(256) void gat_k2(const float* __restrict__ ctx,
                                              const float* __restrict__ Ws,
                                              const float* __restrict__ a) {
    extern __shared__ char sm[];
    float* cs  = (float*)sm;                 // [32][stride 66]
    float* wss = (float*)(sm + K2_WS_OFF);   // [64][64]
    int tid = threadIdx.x;
    int g0 = blockIdx.x * 32;
    int rowT = tid >> 4, colT = tid & 15;
    int r0 = rowT * 2, n0 = colT * 4;
    float acc[2][4];
    #pragma unroll
    for (int i = 0; i < 2; i++)
        #pragma unroll
        for (int c = 0; c < 4; c++) acc[i][c] = 0.f;

    for (int ch = 0; ch < 4; ch++) {
        int fc = ch * 64;
        if (ch) __syncthreads();
        #pragma unroll
        for (int it = 0; it < 2; it++) {
            int lin = tid + it * 256;
            int f4 = lin & 15, r = lin >> 4;
            float4 v = *(const float4*)&ctx[(size_t)(g0 + r) * F_ + fc + f4 * 4];
            float* d = &cs[r * K2_CS_STRIDE + f4 * 4];
            d[0] = v.x; d[1] = v.y; d[2] = v.z; d[3] = v.w;
        }
        #pragma unroll
        for (int it = 0; it < 4; it++) {
            int lin = tid + it * 256;
            int n4 = lin & 15, f = lin >> 4;
            float4 v = *(const float4*)&Ws[(size_t)(fc + f) * FO_ + n4 * 4];
            *(float4*)&wss[f * FO_ + n4 * 4] = v;
        }
        __syncthreads();
        #pragma unroll 4
        for (int f = 0; f < 64; f++) {
            float4 w = *(const float4*)&wss[f * FO_ + n0];
            #pragma unroll
            for (int i = 0; i < 2; i++) {
                float c = cs[(r0 + i) * K2_CS_STRIDE + f];
                acc[i][0] += c * w.x; acc[i][1] += c * w.y;
                acc[i][2] += c * w.z; acc[i][3] += c * w.w;
            }
        }
    }
    __syncthreads();
    float a1c[4];
    #pragma unroll
    for (int c = 0; c < 4; c++) a1c[c] = a[n0 + c];
    float* red = (float*)sm;  // [32][16]
    #pragma unroll
    for (int i = 0; i < 2; i++) {
        float part = acc[i][0] * a1c[0] + acc[i][1] * a1c[1]
                   + acc[i][2] * a1c[2] + acc[i][3] * a1c[3];
        float l0 = acc[i][0] - trunc_bf16(acc[i][0]);
        float l1 = acc[i][1] - trunc_bf16(acc[i][1]);
        float l2 = acc[i][2] - trunc_bf16(acc[i][2]);
        float l3 = acc[i][3] - trunc_bf16(acc[i][3]);
        uint2 hst = make_uint2(pack_hi(acc[i][0], acc[i][1]), pack_hi(acc[i][2], acc[i][3]));
        uint2 lst = make_uint2(pack_rn(l0, l1), pack_rn(l2, l3));
        size_t base = (size_t)(g0 + r0 + i) * FO_ + n0;
        *(uint2*)&g_Vhi[base] = hst;
        *(uint2*)&g_Vlo[base] = lst;
        red[(r0 + i) * 16 + colT] = part;
    }
    __syncthreads();
    if (tid < 32) {
        float s = 0.f;
        #pragma unroll
        for (int j = 0; j < 16; j++) s += red[tid * 16 + j];
        g_EA1[g0 + tid] = __expf(s);
        g_EA2[g0 + tid] = __expf(0.2f * s);
    }
}

// ---------------- K3: EB (w2 inline), grid 256 x 64 rows ----------------
__global__ __launch_bounds__(256) void gat_k3(const float* __restrict__ h,
                                              const float* __restrict__ Wt,
                                              const float* __restrict__ a) {
    __shared__ float w2s[F_];
    int tid = threadIdx.x;
    {
        float acc = 0.f;
        const float* wr = Wt + (size_t)tid * FO_;
        #pragma unroll 8
        for (int o = 0; o < FO_; o++) acc += wr[o] * a[FO_ + o];
        w2s[tid] = acc;
    }
    __syncthreads();
    int lane = tid & 31, w = tid >> 5;
    int rb = blockIdx.x * 64;
    const float4* wp = (const float4*)w2s;
    float4 w0 = wp[lane], w1 = wp[lane + 32];
    #pragma unroll
    for (int it = 0; it < 8; it++) {
        int sg = rb + it * 8 + w;
        const float4* hp = (const float4*)(h + (size_t)sg * F_);
        float4 x0 = hp[lane], x1 = hp[lane + 32];
        float d = x0.x * w0.x + x0.y * w0.y + x0.z * w0.z + x0.w * w0.w
                + x1.x * w1.x + x1.y * w1.y + x1.z * w1.z + x1.w * w1.w;
        #pragma unroll
        for (int off = 16; off > 0; off >>= 1) d += __shfl_xor_sync(0xffffffffu, d, off);
        if (lane == 0) {
            g_EB1[sg] = __expf(d);
            g_EB2[sg] = __expf(0.2f * d);
        }
    }
}

// ---------------- main: 4 M-warps x 4 K-quarters, all streams via cp.async ----------------
__global__ __launch_bounds__(512, 1)
void gat_main(const int* __restrict__ adj, float* __restrict__ out) {
    extern __shared__ char sm[];
    uint32_t smb = smem_u32(sm);
    float* sden = (float*)(sm + SDEN);   // [4][128]

    int tid = threadIdx.x;
    int l = tid & 31, wid = tid >> 5;
    int cta = blockIdx.x;
    int b = cta >> 5;
    int t0 = (cta & 31) * TM_;
    int bN = b * N_;
    int wm = wid & 3;    // rows wm*32 .. wm*32+31
    int kh = wid >> 2;   // 32-s quarter within each 128-s super-block

    int r0 = wm * 32 + (l >> 2);
    int cb = (l & 3) * 2;
    float ea1[4], ea2[4];
    #pragma unroll
    for (int p = 0; p < 4; p++) {
        ea1[p] = g_EA1[bN + t0 + r0 + p * 8];
        ea2[p] = g_EA2[bN + t0 + r0 + p * 8];
    }

    // ---- fill-side thread mappings ----
    // adj: 128 rows x 512B per super-block; thread -> row (tid>>2), 128B part (tid&3)
    int ar = tid >> 2, ap = tid & 3;
    const int* asrc0 = adj + (size_t)(bN + t0 + ar) * N_ + ap * 32;
    uint32_t adst0 = smb + 0 + (uint32_t)(ar * ADJSTRIDE + ap * 128);
    // V: 128 s-rows x 128B; thread -> row (tid>>2), 32B pair (tid&3)
    int vq = tid & 3;
    uint32_t vsw = (uint32_t)((ar * 128 + vq * 32) ^ ((ar & 7) << 4));
    const char* vsh0 = (const char*)g_Vhi + ((size_t)(bN + ar) * FO_) * 2 + vq * 32;
    const char* vsl0 = (const char*)g_Vlo + ((size_t)(bN + ar) * FO_) * 2 + vq * 32;
    // EB: threads 0..63
    const float* ebsrc = (tid < 32) ? (g_EB1 + bN + (tid & 31) * 4) : (g_EB2 + bN + (tid & 31) * 4);
    uint32_t ebdst = smb + EBO + (uint32_t)((tid >> 5) & 1) * 512 + (uint32_t)(tid & 31) * 16;

    // ldmatrix geometry (row = kh*32 + kk*16 + (l&15), colbyte = ng*32 + (l>>4)*16)
    uint32_t lb = (uint32_t)((kh * 32 + (l & 15)) * 128 + (l >> 4) * 16);
    uint32_t swx = (uint32_t)((l & 7) << 4);

    // prologue: fill buffer 0 (super-block 0)
    {
        #pragma unroll
        for (int i = 0; i < 8; i++) cp16(adst0 + i * 16, asrc0 + i * 4);
        uint32_t vd = smb + VOFF + vsw;
        cp16(vd, vsh0);
        cp16(vd ^ 16, vsh0 + 16);
        cp16(vd + 16384, vsl0);
        cp16((vd + 16384) ^ 16, vsl0 + 16);
        if (tid < 64) cp16(ebdst, ebsrc);
        cp_commit();
    }

    float C0[8][4], C1[8][4];
    #pragma unroll
    for (int f = 0; f < 8; f++)
        #pragma unroll
        for (int i = 0; i < 4; i++) { C0[f][i] = 0.f; C1[f][i] = 0.f; }
    float dden[4] = {0.f, 0.f, 0.f, 0.f};

    for (int j = 0; j < 32; j++) {
        if (j < 31) {
            int sn = (j + 1) * 128;
            uint32_t bufn = (uint32_t)((j + 1) & 1);
            const int* as = asrc0 + sn;
            uint32_t ad = adst0 + bufn * ADJBUF;
            #pragma unroll
            for (int i = 0; i < 8; i++) cp16(ad + i * 16, as + i * 4);
            uint32_t vd = smb + VOFF + bufn * VBUF + vsw;
            const char* vh = vsh0 + (size_t)sn * 128;
            const char* vl = vsl0 + (size_t)sn * 128;
            cp16(vd, vh);
            cp16(vd ^ 16, vh + 16);
            cp16(vd + 16384, vl);
            cp16((vd + 16384) ^ 16, vl + 16);
            if (tid < 64) cp16(ebdst + bufn * 1024, ebsrc + sn);
            cp_commit();
            cp_wait<1>();
        } else {
            cp_wait<0>();
        }
        __syncthreads();

        uint32_t buf = (uint32_t)(j & 1);
        const char* abase = sm + buf * ADJBUF;
        uint32_t vbhi = smb + VOFF + buf * VBUF;
        uint32_t vblo = vbhi + 16384;
        const float* EB1b = (const float*)(sm + EBO + buf * 1024);
        const float* EB2b = EB1b + 128;

        #pragma unroll
        for (int kk = 0; kk < 2; kk++) {
            int c0 = kh * 32 + kk * 16 + cb;
            float2 e1a = *(const float2*)&EB1b[c0];
            float2 e1b = *(const float2*)&EB1b[c0 + 8];
            float2 e2a = *(const float2*)&EB2b[c0];
            float2 e2b = *(const float2*)&EB2b[c0 + 8];

            uint32_t hA[4], hB[4], lA[4], lB[4];
            #pragma unroll
            for (int p = 0; p < 4; p++) {
                const char* arow = abase + (r0 + 8 * p) * ADJSTRIDE + c0 * 4;
                int2 A0 = *(const int2*)arow;
                int2 A1 = *(const int2*)(arow + 32);
                float x0, x1, x2, x3;
                x0 = fmaxf(ea1[p] * e1a.x, ea2[p] * e2a.x); x0 = (A0.x > 0) ? x0 : 0.f;
                x1 = fmaxf(ea1[p] * e1a.y, ea2[p] * e2a.y); x1 = (A0.y > 0) ? x1 : 0.f;
                x2 = fmaxf(ea1[p] * e1b.x, ea2[p] * e2b.x); x2 = (A1.x > 0) ? x2 : 0.f;
                x3 = fmaxf(ea1[p] * e1b.y, ea2[p] * e2b.y); x3 = (A1.y > 0) ? x3 : 0.f;
                dden[p] += (x0 + x1) + (x2 + x3);
                hA[p] = pack_hi(x0, x1);
                lA[p] = pack_rn(x0 - trunc_bf16(x0), x1 - trunc_bf16(x1));
                hB[p] = pack_hi(x2, x3);
                lB[p] = pack_rn(x2 - trunc_bf16(x2), x3 - trunc_bf16(x3));
            }
            uint32_t ob = lb + (uint32_t)(kk * 2048);
            #pragma unroll
            for (int ng = 0; ng < 4; ng++) {
                uint32_t off = (ob + (uint32_t)(ng * 32)) ^ swx;
                uint32_t bh[4], bl[4];
                ldsm4t(bh, vbhi + off);
                ldsm4t(bl, vblo + off);
                mma16816(C0[2 * ng],     hA[0], hA[1], hB[0], hB[1], bh[0], bh[1]);
                mma16816(C1[2 * ng],     hA[2], hA[3], hB[2], hB[3], bh[0], bh[1]);
                mma16816(C0[2 * ng + 1], hA[0], hA[1], hB[0], hB[1], bh[2], bh[3]);
                mma16816(C1[2 * ng + 1], hA[2], hA[3], hB[2], hB[3], bh[2], bh[3]);
                mma16816(C0[2 * ng],     lA[0], lA[1], lB[0], lB[1], bh[0], bh[1]);
                mma16816(C1[2 * ng],     lA[2], lA[3], lB[2], lB[3], bh[0], bh[1]);
                mma16816(C0[2 * ng + 1], lA[0], lA[1], lB[0], lB[1], bh[2], bh[3]);
                mma16816(C1[2 * ng + 1], lA[2], lA[3], lB[2], lB[3], bh[2], bh[3]);
                mma16816(C0[2 * ng],     hA[0], hA[1], hB[0], hB[1], bl[0], bl[1]);
                mma16816(C1[2 * ng],     hA[2], hA[3], hB[2], hB[3], bl[0], bl[1]);
                mma16816(C0[2 * ng + 1], hA[0], hA[1], hB[0], hB[1], bl[2], bl[3]);
                mma16816(C1[2 * ng + 1], hA[2], hA[3], hB[2], hB[3], bl[2], bl[3]);
            }
        }
        __syncthreads();
    }

    // ---- epilogue ----
    #pragma unroll
    for (int p = 0; p < 4; p++) {
        dden[p] += __shfl_xor_sync(0xffffffffu, dden[p], 1);
        dden[p] += __shfl_xor_sync(0xffffffffu, dden[p], 2);
    }
    if ((l & 3) == 0) {
        #pragma unroll
        for (int p = 0; p < 4; p++) sden[kh * 128 + r0 + p * 8] = dden[p];
    }
    // kh=1..3 dump partials into adj area: [kh-1][row(128)][64] floats (32KB each)
    if (kh) {
        float* mb = (float*)sm + (size_t)(kh - 1) * 8192;
        #pragma unroll
        for (int g = 0; g < 2; g++) {
            int rr = wm * 32 + g * 16 + (l >> 2);
            float (*Cg)[4] = g ? C1 : C0;
            #pragma unroll
            for (int f = 0; f < 8; f++) {
                *(float2*)&mb[rr * 64 + f * 8 + cb]       = make_float2(Cg[f][0], Cg[f][1]);
                *(float2*)&mb[(rr + 8) * 64 + f * 8 + cb] = make_float2(Cg[f][2], Cg[f][3]);
            }
        }
    }
    __syncthreads();
    if (kh == 0) {
        const float* m1 = (const float*)sm;
        const float* m2 = m1 + 8192;
        const float* m3 = m2 + 8192;
        #pragma unroll
        for (int g = 0; g < 2; g++) {
            int rr = wm * 32 + g * 16 + (l >> 2);
            float rd0 = 1.f / (sden[rr] + sden[128 + rr] + sden[256 + rr] + sden[384 + rr]);
            int rs = rr + 8;
            float rd1 = 1.f / (sden[rs] + sden[128 + rs] + sden[256 + rs] + sden[384 + rs]);
            float (*Cg)[4] = g ? C1 : C0;
            float* o0 = out + (size_t)(bN + t0 + rr) * FO_ + cb;
            float* o1 = out + (size_t)(bN + t0 + rs) * FO_ + cb;
            #pragma unroll
            for (int f = 0; f < 8; f++) {
                int i0 = rr * 64 + f * 8 + cb, i1 = rs * 64 + f * 8 + cb;
                float x0 = (Cg[f][0] + m1[i0] + m2[i0] + m3[i0]) * rd0;
                float x1 = (Cg[f][1] + m1[i0 + 1] + m2[i0 + 1] + m3[i0 + 1]) * rd0;
                float x2 = (Cg[f][2] + m1[i1] + m2[i1] + m3[i1]) * rd1;
                float x3 = (Cg[f][3] + m1[i1 + 1] + m2[i1 + 1] + m3[i1 + 1]) * rd1;
                x0 = (x0 > 0.f) ? x0 : 0.01f * x0;
                x1 = (x1 > 0.f) ? x1 : 0.01f * x1;
                x2 = (x2 > 0.f) ? x2 : 0.01f * x2;
                x3 = (x3 > 0.f) ? x3 : 0.01f * x3;
                *(float2*)o0 = make_float2(x0, x1);
                *(float2*)o1 = make_float2(x2, x3);
                o0 += 8; o1 += 8;
            }
        }
    }
}

// ---------------- launcher ----------------
extern "C" void kernel_launch(void* const* d_in, const int* in_sizes, int n_in,
                              void* d_out, int out_size) {
    const float* h   = (const float*)d_in[0];
    const float* ctx = (const float*)d_in[1];
    const int*   adj = (const int*)d_in[2];
    const float* Ws  = (const float*)d_in[3];
    const float* Wt  = (const float*)d_in[4];
    const float* a   = (const float*)d_in[5];
    float* out = (float*)d_out;

    cudaFuncSetAttribute(gat_k2, cudaFuncAttributeMaxDynamicSharedMemorySize, K2_SMEM);
    cudaFuncSetAttribute(gat_main, cudaFuncAttributeMaxDynamicSharedMemorySize, SMEM_MAIN);

    gat_k2<<<(B_ * N_) / 32, 256, K2_SMEM>>>(ctx, Ws, a);
    gat_k3<<<(B_ * N_) / 64, 256>>>(h, Wt, a);
    gat_main<<<B_ * (N_ / TM_), 512, SMEM_MAIN>>>(adj, out);
}

// round 11
// speedup vs baseline: 1.4754x; 1.4754x over previous
#include <cuda_runtime.h>
#include <cuda_bf16.h>
#include <cstdint>
#include <cstddef>

static constexpr int B_  = 4;
static constexpr int N_  = 4096;
static constexpr int F_  = 256;
static constexpr int FO_ = 64;
static constexpr int TM_ = 128;    // t rows per CTA

// main smem: EB1 16K | EB2 16K | V dbl-buf 2x64K (hi32K+lo32K) | sden 2K
static constexpr int EB1O = 0;
static constexpr int EB2O = 16384;
static constexpr int VO   = 32768;
static constexpr int SDEN = 163840;
static constexpr int SMEM_MAIN = 165888;

// prep smem (k2 role): ctx [128][66] fp32 + Ws [64][64] fp32
static constexpr int PCS_STRIDE = 66;
static constexpr int PWS_OFF = 128 * PCS_STRIDE * 4;      // 33792
static constexpr int PREP_SMEM = PWS_OFF + 64 * 64 * 4;   // 50176

__device__ float g_EA1[B_ * N_];
__device__ float g_EA2[B_ * N_];
__device__ float g_EB1[B_ * N_];
__device__ float g_EB2[B_ * N_];
__device__ __nv_bfloat16 g_Vhi[(size_t)B_ * N_ * FO_];
__device__ __nv_bfloat16 g_Vlo[(size_t)B_ * N_ * FO_];

__device__ __forceinline__ uint32_t smem_u32(const void* p) {
    uint32_t a;
    asm("{ .reg .u64 t; cvta.to.shared.u64 t, %1; cvt.u32.u64 %0, t; }" : "=r"(a) : "l"(p));
    return a;
}
__device__ __forceinline__ uint32_t pack_hi(float a, float b) {
    uint32_t r;
    asm("prmt.b32 %0, %1, %2, 0x7632;" : "=r"(r)
        : "r"(__float_as_uint(a)), "r"(__float_as_uint(b)));
    return r;
}
__device__ __forceinline__ uint32_t pack_rn(float a, float b) {
    uint32_t r;
    asm("cvt.rn.bf16x2.f32 %0, %1, %2;" : "=r"(r) : "f"(b), "f"(a));
    return r;
}
__device__ __forceinline__ float trunc_bf16(float a) {
    return __uint_as_float(__float_as_uint(a) & 0xFFFF0000u);
}
__device__ __forceinline__ void ldsm4t(uint32_t* r, uint32_t addr) {
    asm volatile("ldmatrix.sync.aligned.m8n8.x4.trans.shared.b16 {%0,%1,%2,%3}, [%4];"
        : "=r"(r[0]), "=r"(r[1]), "=r"(r[2]), "=r"(r[3]) : "r"(addr));
}
__device__ __forceinline__ void mma16816(float* c, uint32_t a0, uint32_t a1, uint32_t a2, uint32_t a3,
                                         uint32_t b0, uint32_t b1) {
    asm volatile("mma.sync.aligned.m16n8k16.row.col.f32.bf16.bf16.f32 "
        "{%0,%1,%2,%3}, {%4,%5,%6,%7}, {%8,%9}, {%0,%1,%2,%3};"
        : "+f"(c[0]), "+f"(c[1]), "+f"(c[2]), "+f"(c[3])
        : "r"(a0), "r"(a1), "r"(a2), "r"(a3), "r"(b0), "r"(b1));
}
__device__ __forceinline__ void cp16(uint32_t dst, const void* src) {
    asm volatile("cp.async.cg.shared.global [%0], [%1], 16;" :: "r"(dst), "l"(src) : "memory");
}
__device__ __forceinline__ void cp_commit() { asm volatile("cp.async.commit_group;" ::: "memory"); }
template <int NW>
__device__ __forceinline__ void cp_wait() { asm volatile("cp.async.wait_group %0;" :: "n"(NW) : "memory"); }
__device__ __forceinline__ void pref_l2(const void* p) {
    asm volatile("prefetch.global.L2 [%0];" :: "l"(p));
}

// ---------------- prep: blocks 0..127 = V+EA (128 rows, 512thr); 128..383 = EB ----------------
__global__ __launch_bounds__(512) void gat_prep(const float* __restrict__ h,
                                                const float* __restrict__ ctx,
                                                const float* __restrict__ Ws,
                                                const float* __restrict__ Wt,
                                                const float* __restrict__ a) {
    extern __shared__ char sm[];
    int tid = threadIdx.x;
    int bx = blockIdx.x;
    if (bx < 128) {
        float* cs  = (float*)sm;                // [128][66]
        float* wss = (float*)(sm + PWS_OFF);    // [64][64]
        int g0 = bx * 128;
        int rowT = tid >> 4, colT = tid & 15;   // rowT 0..31
        int r0 = rowT * 4, n0 = colT * 4;
        float acc[4][4];
        #pragma unroll
        for (int i = 0; i < 4; i++)
            #pragma unroll
            for (int c = 0; c < 4; c++) acc[i][c] = 0.f;

        for (int ch = 0; ch < 4; ch++) {
            int fc = ch * 64;
            if (ch) __syncthreads();
            #pragma unroll
            for (int it = 0; it < 4; it++) {
                int lin = tid + it * 512;
                int f4 = lin & 15, r = lin >> 4;
                float4 v = *(const float4*)&ctx[(size_t)(g0 + r) * F_ + fc + f4 * 4];
                float* d = &cs[r * PCS_STRIDE + f4 * 4];
                d[0] = v.x; d[1] = v.y; d[2] = v.z; d[3] = v.w;
            }
            #pragma unroll
            for (int it = 0; it < 2; it++) {
                int lin = tid + it * 512;
                int n4 = lin & 15, f = lin >> 4;
                float4 v = *(const float4*)&Ws[(size_t)(fc + f) * FO_ + n4 * 4];
                *(float4*)&wss[f * FO_ + n4 * 4] = v;
            }
            __syncthreads();
            #pragma unroll 4
            for (int f = 0; f < 64; f++) {
                float4 w = *(const float4*)&wss[f * FO_ + n0];
                #pragma unroll
                for (int i = 0; i < 4; i++) {
                    float c = cs[(r0 + i) * PCS_STRIDE + f];
                    acc[i][0] += c * w.x; acc[i][1] += c * w.y;
                    acc[i][2] += c * w.z; acc[i][3] += c * w.w;
                }
            }
        }
        __syncthreads();
        float a1c[4];
        #pragma unroll
        for (int c = 0; c < 4; c++) a1c[c] = a[n0 + c];
        float* red = (float*)sm;  // [128][16]
        #pragma unroll
        for (int i = 0; i < 4; i++) {
            float part = acc[i][0] * a1c[0] + acc[i][1] * a1c[1]
                       + acc[i][2] * a1c[2] + acc[i][3] * a1c[3];
            float l0 = acc[i][0] - trunc_bf16(acc[i][0]);
            float l1 = acc[i][1] - trunc_bf16(acc[i][1]);
            float l2 = acc[i][2] - trunc_bf16(acc[i][2]);
            float l3 = acc[i][3] - trunc_bf16(acc[i][3]);
            uint2 hst = make_uint2(pack_hi(acc[i][0], acc[i][1]), pack_hi(acc[i][2], acc[i][3]));
            uint2 lst = make_uint2(pack_rn(l0, l1), pack_rn(l2, l3));
            size_t base = (size_t)(g0 + r0 + i) * FO_ + n0;
            *(uint2*)&g_Vhi[base] = hst;
            *(uint2*)&g_Vlo[base] = lst;
            red[(r0 + i) * 16 + colT] = part;
        }
        __syncthreads();
        if (tid < 128) {
            float s = 0.f;
            #pragma unroll
            for (int j = 0; j < 16; j++) s += red[tid * 16 + j];
            g_EA1[g0 + tid] = __expf(s);
            g_EA2[g0 + tid] = __expf(0.2f * s);
        }
    } else {
        // EB role: 64 rows per block, w2 computed inline
        float* w2s = (float*)sm;  // 256 floats
        if (tid < 256) {
            float acc = 0.f;
            const float* wr = Wt + (size_t)tid * FO_;
            #pragma unroll 8
            for (int o = 0; o < FO_; o++) acc += wr[o] * a[FO_ + o];
            w2s[tid] = acc;
        }
        __syncthreads();
        int lane = tid & 31, w = tid >> 5;   // 16 warps
        int rb = (bx - 128) * 64;
        const float4* wp = (const float4*)w2s;
        float4 w0 = wp[lane], w1 = wp[lane + 32];
        #pragma unroll
        for (int it = 0; it < 4; it++) {
            int sg = rb + it * 16 + w;
            const float4* hp = (const float4*)(h + (size_t)sg * F_);
            float4 x0 = hp[lane], x1 = hp[lane + 32];
            float d = x0.x * w0.x + x0.y * w0.y + x0.z * w0.z + x0.w * w0.w
                    + x1.x * w1.x + x1.y * w1.y + x1.z * w1.z + x1.w * w1.w;
            #pragma unroll
            for (int off = 16; off > 0; off >>= 1) d += __shfl_xor_sync(0xffffffffu, d, off);
            if (lane == 0) {
                g_EB1[sg] = __expf(d);
                g_EB2[sg] = __expf(0.2f * d);
            }
        }
    }
}

// ---------------- main: 4 M-warps x 4 K-quarters, V cp.async dbl-buf, adj regs + L2 prefetch ----------------
__global__ __launch_bounds__(512, 1)
void gat_main(const int* __restrict__ adj, float* __restrict__ out) {
    extern __shared__ char sm[];
    uint32_t smb = smem_u32(sm);
    float* EB1s = (float*)(sm + EB1O);
    float* EB2s = (float*)(sm + EB2O);
    float* sden = (float*)(sm + SDEN);   // [4][128]

    int tid = threadIdx.x;
    int l = tid & 31, wid = tid >> 5;
    int cta = blockIdx.x;
    int b = cta >> 5;
    int t0 = (cta & 31) * TM_;
    int bN = b * N_;
    int wm = wid & 3;    // rows wm*32 .. wm*32+31
    int kh = wid >> 2;   // 64-s quarter within each 256-s super-block

    // stage EB (whole batch) into smem
    {
        const float4* s1 = (const float4*)(g_EB1 + bN);
        const float4* s2 = (const float4*)(g_EB2 + bN);
        float4* d1 = (float4*)EB1s;
        float4* d2 = (float4*)EB2s;
        d1[tid] = s1[tid]; d1[tid + 512] = s1[tid + 512];
        d2[tid] = s2[tid]; d2[tid + 512] = s2[tid + 512];
    }

    int r0 = wm * 32 + (l >> 2);
    int cb = (l & 3) * 2;
    float ea1[4], ea2[4];
    #pragma unroll
    for (int p = 0; p < 4; p++) {
        ea1[p] = g_EA1[bN + t0 + r0 + p * 8];
        ea2[p] = g_EA2[bN + t0 + r0 + p * 8];
    }
    const int* adjB = adj + (size_t)(bN + t0 + r0) * N_;

    // cp.async V mapping
    int vr = tid >> 3, vc = tid & 7;
    uint32_t vdsw = (uint32_t)((vr * 128 + vc * 16) ^ ((vr & 7) << 4));
    const char* vsh = (const char*)(g_Vhi + ((size_t)bN + vr) * FO_ + vc * 8);
    const char* vsl = (const char*)(g_Vlo + ((size_t)bN + vr) * FO_ + vc * 8);

    // ldmatrix geometry
    uint32_t lb = (uint32_t)((kh * 64 + (l & 15)) * 128 + (l >> 4) * 16);
    uint32_t swx = (uint32_t)((l & 7) << 4);

    // prologue: V super-block 0
    {
        uint32_t d = smb + VO + vdsw;
        #pragma unroll
        for (int rho = 0; rho < 4; rho++) {
            cp16(d + rho * 8192, vsh + rho * 8192);
            cp16(d + 32768 + rho * 8192, vsl + rho * 8192);
        }
        cp_commit();
    }
    // adj prefetch (j=0, kk=0)
    int2 ajn[8];
    {
        int c0 = kh * 64 + cb;
        #pragma unroll
        for (int p = 0; p < 4; p++) {
            ajn[2 * p]     = *(const int2*)(adjB + (size_t)p * 8 * N_ + c0);
            ajn[2 * p + 1] = *(const int2*)(adjB + (size_t)p * 8 * N_ + c0 + 8);
        }
    }
    // L2 prefetch of super-block 0 handled by demand; prefetch j=1 below.

    float C0[8][4], C1[8][4];
    #pragma unroll
    for (int f = 0; f < 8; f++)
        #pragma unroll
        for (int i = 0; i < 4; i++) { C0[f][i] = 0.f; C1[f][i] = 0.f; }
    float dden[4] = {0.f, 0.f, 0.f, 0.f};

    for (int j = 0; j < 16; j++) {
        if (j < 15) {
            // fill next V buffer, then wait for current
            uint32_t d = smb + VO + (uint32_t)(((j + 1) & 1) * 65536) + vdsw;
            const char* sh = vsh + (size_t)(j + 1) * 32768;
            const char* sl = vsl + (size_t)(j + 1) * 32768;
            #pragma unroll
            for (int rho = 0; rho < 4; rho++) {
                cp16(d + rho * 8192, sh + rho * 8192);
                cp16(d + 32768 + rho * 8192, sl + rho * 8192);
            }
            cp_commit();
            // L2-prefetch next super-block's adj (exact coverage, no duplicates)
            if ((l & 3) == 0) {
                int sn2 = (j + 1) * 256 + kh * 64;
                #pragma unroll
                for (int p = 0; p < 4; p++) {
                    const char* pf = (const char*)(adjB + (size_t)p * 8 * N_ + sn2);
                    pref_l2(pf);
                    pref_l2(pf + 128);
                }
            }
            cp_wait<1>();
        } else {
            cp_wait<0>();
        }
        __syncthreads();

        uint32_t vbhi = smb + VO + (uint32_t)((j & 1) * 65536);
        uint32_t vblo = vbhi + 32768;
        int sj = j * 256 + kh * 64;

        #pragma unroll
        for (int kk = 0; kk < 4; kk++) {
            int c0 = sj + kk * 16 + cb;
            // consume-copy then immediately issue next-kk loads (early issue for latency)
            int2 aj[8];
            #pragma unroll
            for (int q = 0; q < 8; q++) aj[q] = ajn[q];
            {
                int cn = (kk < 3) ? (c0 + 16) : ((j < 15) ? (c0 + 208) : c0);
                #pragma unroll
                for (int p = 0; p < 4; p++) {
                    ajn[2 * p]     = *(const int2*)(adjB + (size_t)p * 8 * N_ + cn);
                    ajn[2 * p + 1] = *(const int2*)(adjB + (size_t)p * 8 * N_ + cn + 8);
                }
            }
            float2 e1a = *(const float2*)&EB1s[c0];
            float2 e1b = *(const float2*)&EB1s[c0 + 8];
            float2 e2a = *(const float2*)&EB2s[c0];
            float2 e2b = *(const float2*)&EB2s[c0 + 8];

            uint32_t hA[4], hB[4], lA[4], lB[4];
            #pragma unroll
            for (int p = 0; p < 4; p++) {
                int2 A0 = aj[2 * p], A1 = aj[2 * p + 1];
                float x0, x1, x2, x3;
                x0 = fmaxf(ea1[p] * e1a.x, ea2[p] * e2a.x); x0 = (A0.x > 0) ? x0 : 0.f;
                x1 = fmaxf(ea1[p] * e1a.y, ea2[p] * e2a.y); x1 = (A0.y > 0) ? x1 : 0.f;
                x2 = fmaxf(ea1[p] * e1b.x, ea2[p] * e2b.x); x2 = (A1.x > 0) ? x2 : 0.f;
                x3 = fmaxf(ea1[p] * e1b.y, ea2[p] * e2b.y); x3 = (A1.y > 0) ? x3 : 0.f;
                dden[p] += (x0 + x1) + (x2 + x3);
                hA[p] = pack_hi(x0, x1);
                lA[p] = pack_rn(x0 - trunc_bf16(x0), x1 - trunc_bf16(x1));
                hB[p] = pack_hi(x2, x3);
                lB[p] = pack_rn(x2 - trunc_bf16(x2), x3 - trunc_bf16(x3));
            }
            uint32_t ob = lb + (uint32_t)(kk * 2048);
            #pragma unroll
            for (int ng = 0; ng < 4; ng++) {
                uint32_t off = (ob + (uint32_t)(ng * 32)) ^ swx;
                uint32_t bh[4], bl[4];
                ldsm4t(bh, vbhi + off);
                ldsm4t(bl, vblo + off);
                mma16816(C0[2 * ng],     hA[0], hA[1], hB[0], hB[1], bh[0], bh[1]);
                mma16816(C1[2 * ng],     hA[2], hA[3], hB[2], hB[3], bh[0], bh[1]);
                mma16816(C0[2 * ng + 1], hA[0], hA[1], hB[0], hB[1], bh[2], bh[3]);
                mma16816(C1[2 * ng + 1], hA[2], hA[3], hB[2], hB[3], bh[2], bh[3]);
                mma16816(C0[2 * ng],     lA[0], lA[1], lB[0], lB[1], bh[0], bh[1]);
                mma16816(C1[2 * ng],     lA[2], lA[3], lB[2], lB[3], bh[0], bh[1]);
                mma16816(C0[2 * ng + 1], lA[0], lA[1], lB[0], lB[1], bh[2], bh[3]);
                mma16816(C1[2 * ng + 1], lA[2], lA[3], lB[2], lB[3], bh[2], bh[3]);
                mma16816(C0[2 * ng],     hA[0], hA[1], hB[0], hB[1], bl[0], bl[1]);
                mma16816(C1[2 * ng],     hA[2], hA[3], hB[2], hB[3], bl[0], bl[1]);
                mma16816(C0[2 * ng + 1], hA[0], hA[1], hB[0], hB[1], bl[2], bl[3]);
                mma16816(C1[2 * ng + 1], hA[2], hA[3], hB[2], hB[3], bl[2], bl[3]);
            }
        }
        __syncthreads();
    }

    // ---- epilogue ----
    #pragma unroll
    for (int p = 0; p < 4; p++) {
        dden[p] += __shfl_xor_sync(0xffffffffu, dden[p], 1);
        dden[p] += __shfl_xor_sync(0xffffffffu, dden[p], 2);
    }
    if ((l & 3) == 0) {
        #pragma unroll
        for (int p = 0; p < 4; p++) sden[kh * 128 + r0 + p * 8] = dden[p];
    }
    // kh=1..3 dump partials into V area: [kh-1][row(128)][64] floats
    if (kh) {
        float* mb = (float*)(sm + VO) + (size_t)(kh - 1) * 8192;
        #pragma unroll
        for (int g = 0; g < 2; g++) {
            int rr = wm * 32 + g * 16 + (l >> 2);
            float (*Cg)[4] = g ? C1 : C0;
            #pragma unroll
            for (int f = 0; f < 8; f++) {
                *(float2*)&mb[rr * 64 + f * 8 + cb]       = make_float2(Cg[f][0], Cg[f][1]);
                *(float2*)&mb[(rr + 8) * 64 + f * 8 + cb] = make_float2(Cg[f][2], Cg[f][3]);
            }
        }
    }
    __syncthreads();
    if (kh == 0) {
        const float* m1 = (const float*)(sm + VO);
        const float* m2 = m1 + 8192;
        const float* m3 = m2 + 8192;
        #pragma unroll
        for (int g = 0; g < 2; g++) {
            int rr = wm * 32 + g * 16 + (l >> 2);
            float rd0 = 1.f / (sden[rr] + sden[128 + rr] + sden[256 + rr] + sden[384 + rr]);
            int rs = rr + 8;
            float rd1 = 1.f / (sden[rs] + sden[128 + rs] + sden[256 + rs] + sden[384 + rs]);
            float (*Cg)[4] = g ? C1 : C0;
            float* o0 = out + (size_t)(bN + t0 + rr) * FO_ + cb;
            float* o1 = out + (size_t)(bN + t0 + rs) * FO_ + cb;
            #pragma unroll
            for (int f = 0; f < 8; f++) {
                int i0 = rr * 64 + f * 8 + cb, i1 = rs * 64 + f * 8 + cb;
                float x0 = (Cg[f][0] + m1[i0] + m2[i0] + m3[i0]) * rd0;
                float x1 = (Cg[f][1] + m1[i0 + 1] + m2[i0 + 1] + m3[i0 + 1]) * rd0;
                float x2 = (Cg[f][2] + m1[i1] + m2[i1] + m3[i1]) * rd1;
                float x3 = (Cg[f][3] + m1[i1 + 1] + m2[i1 + 1] + m3[i1 + 1]) * rd1;
                x0 = (x0 > 0.f) ? x0 : 0.01f * x0;
                x1 = (x1 > 0.f) ? x1 : 0.01f * x1;
                x2 = (x2 > 0.f) ? x2 : 0.01f * x2;
                x3 = (x3 > 0.f) ? x3 : 0.01f * x3;
                *(float2*)o0 = make_float2(x0, x1);
                *(float2*)o1 = make_float2(x2, x3);
                o0 += 8; o1 += 8;
            }
        }
    }
}

// ---------------- launcher ----------------
extern "C" void kernel_launch(void* const* d_in, const int* in_sizes, int n_in,
                              void* d_out, int out_size) {
    const float* h   = (const float*)d_in[0];
    const float* ctx = (const float*)d_in[1];
    const int*   adj = (const int*)d_in[2];
    const float* Ws  = (const float*)d_in[3];
    const float* Wt  = (const float*)d_in[4];
    const float* a   = (const float*)d_in[5];
    float* out = (float*)d_out;

    cudaFuncSetAttribute(gat_prep, cudaFuncAttributeMaxDynamicSharedMemorySize, PREP_SMEM);
    cudaFuncSetAttribute(gat_main, cudaFuncAttributeMaxDynamicSharedMemorySize, SMEM_MAIN);

    gat_prep<<<384, 512, PREP_SMEM>>>(h, ctx, Ws, Wt, a);
    gat_main<<<B_ * (N_ / TM_), 512, SMEM_MAIN>>>(adj, out);
}

// round 12
// speedup vs baseline: 1.5913x; 1.0785x over previous
#include <cuda_runtime.h>
#include <cuda_fp16.h>
#include <cstdint>
#include <cstddef>

static constexpr int B_  = 4;
static constexpr int N_  = 4096;
static constexpr int F_  = 256;
static constexpr int FO_ = 64;
static constexpr int TM_ = 128;    // t rows per CTA

// main smem: EB1 16K | EB2 16K | V dbl-buf 2x64K (hi32K+lo32K) | sden 2K
static constexpr int EB1O = 0;
static constexpr int EB2O = 16384;
static constexpr int VO   = 32768;
static constexpr int SDEN = 163840;
static constexpr int SMEM_MAIN = 165888;

// prep smem (V role): ctx [128][66] fp32 + Ws [64][64] fp32
static constexpr int PCS_STRIDE = 66;
static constexpr int PWS_OFF = 128 * PCS_STRIDE * 4;      // 33792
static constexpr int PREP_SMEM = PWS_OFF + 64 * 64 * 4;   // 50176

__device__ float g_EA1[B_ * N_];
__device__ float g_EA2[B_ * N_];
__device__ float g_EB1[B_ * N_];
__device__ float g_EB2[B_ * N_];
__device__ float g_pm1[256];
__device__ float g_pm2[256];
__device__ __half g_Vhi[(size_t)B_ * N_ * FO_];
__device__ __half g_Vlo[(size_t)B_ * N_ * FO_];

__device__ __forceinline__ uint32_t smem_u32(const void* p) {
    uint32_t a;
    asm("{ .reg .u64 t; cvta.to.shared.u64 t, %1; cvt.u32.u64 %0, t; }" : "=r"(a) : "l"(p));
    return a;
}
// pack two fp32 -> f16x2 (round-nearest): low half <- a, high half <- b
__device__ __forceinline__ uint32_t pack_h2(float a, float b) {
    uint32_t r;
    asm("cvt.rn.f16x2.f32 %0, %1, %2;" : "=r"(r) : "f"(b), "f"(a));
    return r;
}
__device__ __forceinline__ void ldsm4t(uint32_t* r, uint32_t addr) {
    asm volatile("ldmatrix.sync.aligned.m8n8.x4.trans.shared.b16 {%0,%1,%2,%3}, [%4];"
        : "=r"(r[0]), "=r"(r[1]), "=r"(r[2]), "=r"(r[3]) : "r"(addr));
}
__device__ __forceinline__ void mma16816h(float* c, uint32_t a0, uint32_t a1, uint32_t a2, uint32_t a3,
                                          uint32_t b0, uint32_t b1) {
    asm volatile("mma.sync.aligned.m16n8k16.row.col.f32.f16.f16.f32 "
        "{%0,%1,%2,%3}, {%4,%5,%6,%7}, {%8,%9}, {%0,%1,%2,%3};"
        : "+f"(c[0]), "+f"(c[1]), "+f"(c[2]), "+f"(c[3])
        : "r"(a0), "r"(a1), "r"(a2), "r"(a3), "r"(b0), "r"(b1));
}
__device__ __forceinline__ void cp16(uint32_t dst, const void* src) {
    asm volatile("cp.async.cg.shared.global [%0], [%1], 16;" :: "r"(dst), "l"(src) : "memory");
}
__device__ __forceinline__ void cp_commit() { asm volatile("cp.async.commit_group;" ::: "memory"); }
template <int NW>
__device__ __forceinline__ void cp_wait() { asm volatile("cp.async.wait_group %0;" :: "n"(NW) : "memory"); }
__device__ __forceinline__ void pref_l2(const void* p) {
    asm volatile("prefetch.global.L2 [%0];" :: "l"(p));
}

// ---------------- prep: blocks 0..127 = V(fp16 hi/lo)+EA; 128..383 = EB + per-block max ----------------
__global__ __launch_bounds__(512) void gat_prep(const float* __restrict__ h,
                                                const float* __restrict__ ctx,
                                                const float* __restrict__ Ws,
                                                const float* __restrict__ Wt,
                                                const float* __restrict__ a) {
    extern __shared__ char sm[];
    int tid = threadIdx.x;
    int bx = blockIdx.x;
    if (bx < 128) {
        float* cs  = (float*)sm;                // [128][66]
        float* wss = (float*)(sm + PWS_OFF);    // [64][64]
        int g0 = bx * 128;
        int rowT = tid >> 4, colT = tid & 15;   // rowT 0..31
        int r0 = rowT * 4, n0 = colT * 4;
        float acc[4][4];
        #pragma unroll
        for (int i = 0; i < 4; i++)
            #pragma unroll
            for (int c = 0; c < 4; c++) acc[i][c] = 0.f;

        for (int ch = 0; ch < 4; ch++) {
            int fc = ch * 64;
            if (ch) __syncthreads();
            #pragma unroll
            for (int it = 0; it < 4; it++) {
                int lin = tid + it * 512;
                int f4 = lin & 15, r = lin >> 4;
                float4 v = *(const float4*)&ctx[(size_t)(g0 + r) * F_ + fc + f4 * 4];
                float* d = &cs[r * PCS_STRIDE + f4 * 4];
                d[0] = v.x; d[1] = v.y; d[2] = v.z; d[3] = v.w;
            }
            #pragma unroll
            for (int it = 0; it < 2; it++) {
                int lin = tid + it * 512;
                int n4 = lin & 15, f = lin >> 4;
                float4 v = *(const float4*)&Ws[(size_t)(fc + f) * FO_ + n4 * 4];
                *(float4*)&wss[f * FO_ + n4 * 4] = v;
            }
            __syncthreads();
            #pragma unroll 4
            for (int f = 0; f < 64; f++) {
                float4 w = *(const float4*)&wss[f * FO_ + n0];
                #pragma unroll
                for (int i = 0; i < 4; i++) {
                    float c = cs[(r0 + i) * PCS_STRIDE + f];
                    acc[i][0] += c * w.x; acc[i][1] += c * w.y;
                    acc[i][2] += c * w.z; acc[i][3] += c * w.w;
                }
            }
        }
        __syncthreads();
        float a1c[4];
        #pragma unroll
        for (int c = 0; c < 4; c++) a1c[c] = a[n0 + c];
        float* red = (float*)sm;  // [128][16]
        #pragma unroll
        for (int i = 0; i < 4; i++) {
            float part = acc[i][0] * a1c[0] + acc[i][1] * a1c[1]
                       + acc[i][2] * a1c[2] + acc[i][3] * a1c[3];
            float h0 = __half2float(__float2half_rn(acc[i][0]));
            float h1 = __half2float(__float2half_rn(acc[i][1]));
            float h2 = __half2float(__float2half_rn(acc[i][2]));
            float h3 = __half2float(__float2half_rn(acc[i][3]));
            uint2 hst = make_uint2(pack_h2(acc[i][0], acc[i][1]), pack_h2(acc[i][2], acc[i][3]));
            uint2 lst = make_uint2(pack_h2(acc[i][0] - h0, acc[i][1] - h1),
                                   pack_h2(acc[i][2] - h2, acc[i][3] - h3));
            size_t base = (size_t)(g0 + r0 + i) * FO_ + n0;
            *(uint2*)&g_Vhi[base] = hst;
            *(uint2*)&g_Vlo[base] = lst;
            red[(r0 + i) * 16 + colT] = part;
        }
        __syncthreads();
        if (tid < 128) {
            float s = 0.f;
            #pragma unroll
            for (int j = 0; j < 16; j++) s += red[tid * 16 + j];
            g_EA1[g0 + tid] = __expf(s);
            g_EA2[g0 + tid] = __expf(0.2f * s);
        }
    } else {
        // EB role: 64 rows per block, w2 inline, plus per-block max of EB1/EB2
        float* w2s = (float*)sm;  // 256 floats
        if (tid < 256) {
            float acc = 0.f;
            const float* wr = Wt + (size_t)tid * FO_;
            #pragma unroll 8
            for (int o = 0; o < FO_; o++) acc += wr[o] * a[FO_ + o];
            w2s[tid] = acc;
        }
        __syncthreads();
        int lane = tid & 31, w = tid >> 5;   // 16 warps
        int rb = (bx - 128) * 64;
        const float4* wp = (const float4*)w2s;
        float4 w0 = wp[lane], w1 = wp[lane + 32];
        float m1 = 0.f, m2 = 0.f;
        #pragma unroll
        for (int it = 0; it < 4; it++) {
            int sg = rb + it * 16 + w;
            const float4* hp = (const float4*)(h + (size_t)sg * F_);
            float4 x0 = hp[lane], x1 = hp[lane + 32];
            float d = x0.x * w0.x + x0.y * w0.y + x0.z * w0.z + x0.w * w0.w
                    + x1.x * w1.x + x1.y * w1.y + x1.z * w1.z + x1.w * w1.w;
            #pragma unroll
            for (int off = 16; off > 0; off >>= 1) d += __shfl_xor_sync(0xffffffffu, d, off);
            if (lane == 0) {
                float e1 = __expf(d), e2 = __expf(0.2f * d);
                g_EB1[sg] = e1;
                g_EB2[sg] = e2;
                m1 = fmaxf(m1, e1);
                m2 = fmaxf(m2, e2);
            }
        }
        __syncthreads();   // w2s reads done; reuse smem for max reduce
        float* wm = (float*)sm;  // [2][16]
        if (lane == 0) { wm[w] = m1; wm[16 + w] = m2; }
        __syncthreads();
        if (tid < 2) {
            const float* src = wm + tid * 16;
            float m = src[0];
            #pragma unroll
            for (int i = 1; i < 16; i++) m = fmaxf(m, src[i]);
            if (tid == 0) g_pm1[bx - 128] = m;
            else          g_pm2[bx - 128] = m;
        }
    }
}

// ---------------- main: 4 M-warps x 4 K-quarters, fp16 P single-term, V hi/lo ----------------
__global__ __launch_bounds__(512, 1)
void gat_main(const int* __restrict__ adj, float* __restrict__ out) {
    extern __shared__ char sm[];
    uint32_t smb = smem_u32(sm);
    float* EB1s = (float*)(sm + EB1O);
    float* EB2s = (float*)(sm + EB2O);
    float* sden = (float*)(sm + SDEN);   // [4][128] (also used for max staging)

    int tid = threadIdx.x;
    int l = tid & 31, wid = tid >> 5;
    int cta = blockIdx.x;
    int b = cta >> 5;
    int t0 = (cta & 31) * TM_;
    int bN = b * N_;
    int wm = wid & 3;    // rows wm*32 .. wm*32+31
    int kh = wid >> 2;   // 64-s quarter within each 256-s super-block

    // stage EB (whole batch) into smem; stage per-batch partial maxes
    {
        const float4* s1 = (const float4*)(g_EB1 + bN);
        const float4* s2 = (const float4*)(g_EB2 + bN);
        float4* d1 = (float4*)EB1s;
        float4* d2 = (float4*)EB2s;
        d1[tid] = s1[tid]; d1[tid + 512] = s1[tid + 512];
        d2[tid] = s2[tid]; d2[tid + 512] = s2[tid + 512];
        if (tid < 64) {
            sden[tid]      = g_pm1[b * 64 + tid];
            sden[64 + tid] = g_pm2[b * 64 + tid];
        }
    }
    __syncthreads();
    float mB1 = sden[0], mB2 = sden[64];
    #pragma unroll
    for (int i = 1; i < 64; i++) {
        mB1 = fmaxf(mB1, sden[i]);
        mB2 = fmaxf(mB2, sden[64 + i]);
    }

    int r0 = wm * 32 + (l >> 2);
    int cb = (l & 3) * 2;
    float ea1[4], ea2[4];
    #pragma unroll
    for (int p = 0; p < 4; p++) {
        float e1 = g_EA1[bN + t0 + r0 + p * 8];
        float e2 = g_EA2[bN + t0 + r0 + p * 8];
        // per-row power-of-2 scale: bound = max possible P for this row; scaled bound in [2^13, 2^14)
        float M = fmaxf(e1 * mB1, e2 * mB2);
        uint32_t eb = (__float_as_uint(M) >> 23) & 0xFFu;
        float s = __uint_as_float((267u - eb) << 23);
        ea1[p] = e1 * s;
        ea2[p] = e2 * s;
    }
    const int* adjB = adj + (size_t)(bN + t0 + r0) * N_;

    // cp.async V mapping (fp16 rows: 64 halves = 128B, same byte layout as before)
    int vr = tid >> 3, vc = tid & 7;
    uint32_t vdsw = (uint32_t)((vr * 128 + vc * 16) ^ ((vr & 7) << 4));
    const char* vsh = (const char*)(g_Vhi + ((size_t)bN + vr) * FO_ + vc * 8);
    const char* vsl = (const char*)(g_Vlo + ((size_t)bN + vr) * FO_ + vc * 8);

    // ldmatrix geometry
    uint32_t lb = (uint32_t)((kh * 64 + (l & 15)) * 128 + (l >> 4) * 16);
    uint32_t swx = (uint32_t)((l & 7) << 4);

    // prologue: V super-block 0
    {
        uint32_t d = smb + VO + vdsw;
        #pragma unroll
        for (int rho = 0; rho < 4; rho++) {
            cp16(d + rho * 8192, vsh + rho * 8192);
            cp16(d + 32768 + rho * 8192, vsl + rho * 8192);
        }
        cp_commit();
    }
    // adj prefetch (j=0, kk=0)
    int2 ajn[8];
    {
        int c0 = kh * 64 + cb;
        #pragma unroll
        for (int p = 0; p < 4; p++) {
            ajn[2 * p]     = *(const int2*)(adjB + (size_t)p * 8 * N_ + c0);
            ajn[2 * p + 1] = *(const int2*)(adjB + (size_t)p * 8 * N_ + c0 + 8);
        }
    }

    float C0[8][4], C1[8][4];
    #pragma unroll
    for (int f = 0; f < 8; f++)
        #pragma unroll
        for (int i = 0; i < 4; i++) { C0[f][i] = 0.f; C1[f][i] = 0.f; }
    float dden[4] = {0.f, 0.f, 0.f, 0.f};

    for (int j = 0; j < 16; j++) {
        if (j < 15) {
            uint32_t d = smb + VO + (uint32_t)(((j + 1) & 1) * 65536) + vdsw;
            const char* sh = vsh + (size_t)(j + 1) * 32768;
            const char* sl = vsl + (size_t)(j + 1) * 32768;
            #pragma unroll
            for (int rho = 0; rho < 4; rho++) {
                cp16(d + rho * 8192, sh + rho * 8192);
                cp16(d + 32768 + rho * 8192, sl + rho * 8192);
            }
            cp_commit();
            if ((l & 3) == 0) {
                int sn2 = (j + 1) * 256 + kh * 64;
                #pragma unroll
                for (int p = 0; p < 4; p++) {
                    const char* pf = (const char*)(adjB + (size_t)p * 8 * N_ + sn2);
                    pref_l2(pf);
                    pref_l2(pf + 128);
                }
            }
            cp_wait<1>();
        } else {
            cp_wait<0>();
        }
        __syncthreads();

        uint32_t vbhi = smb + VO + (uint32_t)((j & 1) * 65536);
        uint32_t vblo = vbhi + 32768;
        int sj = j * 256 + kh * 64;

        #pragma unroll
        for (int kk = 0; kk < 4; kk++) {
            int c0 = sj + kk * 16 + cb;
            int2 aj[8];
            #pragma unroll
            for (int q = 0; q < 8; q++) aj[q] = ajn[q];
            {
                int cn = (kk < 3) ? (c0 + 16) : ((j < 15) ? (c0 + 208) : c0);
                #pragma unroll
                for (int p = 0; p < 4; p++) {
                    ajn[2 * p]     = *(const int2*)(adjB + (size_t)p * 8 * N_ + cn);
                    ajn[2 * p + 1] = *(const int2*)(adjB + (size_t)p * 8 * N_ + cn + 8);
                }
            }
            float2 e1a = *(const float2*)&EB1s[c0];
            float2 e1b = *(const float2*)&EB1s[c0 + 8];
            float2 e2a = *(const float2*)&EB2s[c0];
            float2 e2b = *(const float2*)&EB2s[c0 + 8];

            uint32_t hA[4], hB[4];
            #pragma unroll
            for (int p = 0; p < 4; p++) {
                int2 A0 = aj[2 * p], A1 = aj[2 * p + 1];
                float x0, x1, x2, x3;
                x0 = fmaxf(ea1[p] * e1a.x, ea2[p] * e2a.x); x0 = (A0.x > 0) ? x0 : 0.f;
                x1 = fmaxf(ea1[p] * e1a.y, ea2[p] * e2a.y); x1 = (A0.y > 0) ? x1 : 0.f;
                x2 = fmaxf(ea1[p] * e1b.x, ea2[p] * e2b.x); x2 = (A1.x > 0) ? x2 : 0.f;
                x3 = fmaxf(ea1[p] * e1b.y, ea2[p] * e2b.y); x3 = (A1.y > 0) ? x3 : 0.f;
                dden[p] += (x0 + x1) + (x2 + x3);
                hA[p] = pack_h2(x0, x1);
                hB[p] = pack_h2(x2, x3);
            }
            uint32_t ob = lb + (uint32_t)(kk * 2048);
            #pragma unroll
            for (int ng = 0; ng < 4; ng++) {
                uint32_t off = (ob + (uint32_t)(ng * 32)) ^ swx;
                uint32_t bh[4], bl[4];
                ldsm4t(bh, vbhi + off);
                ldsm4t(bl, vblo + off);
                mma16816h(C0[2 * ng],     hA[0], hA[1], hB[0], hB[1], bh[0], bh[1]);
                mma16816h(C1[2 * ng],     hA[2], hA[3], hB[2], hB[3], bh[0], bh[1]);
                mma16816h(C0[2 * ng + 1], hA[0], hA[1], hB[0], hB[1], bh[2], bh[3]);
                mma16816h(C1[2 * ng + 1], hA[2], hA[3], hB[2], hB[3], bh[2], bh[3]);
                mma16816h(C0[2 * ng],     hA[0], hA[1], hB[0], hB[1], bl[0], bl[1]);
                mma16816h(C1[2 * ng],     hA[2], hA[3], hB[2], hB[3], bl[0], bl[1]);
                mma16816h(C0[2 * ng + 1], hA[0], hA[1], hB[0], hB[1], bl[2], bl[3]);
                mma16816h(C1[2 * ng + 1], hA[2], hA[3], hB[2], hB[3], bl[2], bl[3]);
            }
        }
        __syncthreads();
    }

    // ---- epilogue ----
    #pragma unroll
    for (int p = 0; p < 4; p++) {
        dden[p] += __shfl_xor_sync(0xffffffffu, dden[p], 1);
        dden[p] += __shfl_xor_sync(0xffffffffu, dden[p], 2);
    }
    if ((l & 3) == 0) {
        #pragma unroll
        for (int p = 0; p < 4; p++) sden[kh * 128 + r0 + p * 8] = dden[p];
    }
    // kh=1..3 dump partials into V area: [kh-1][row(128)][64] floats
    if (kh) {
        float* mb = (float*)(sm + VO) + (size_t)(kh - 1) * 8192;
        #pragma unroll
        for (int g = 0; g < 2; g++) {
            int rr = wm * 32 + g * 16 + (l >> 2);
            float (*Cg)[4] = g ? C1 : C0;
            #pragma unroll
            for (int f = 0; f < 8; f++) {
                *(float2*)&mb[rr * 64 + f * 8 + cb]       = make_float2(Cg[f][0], Cg[f][1]);
                *(float2*)&mb[(rr + 8) * 64 + f * 8 + cb] = make_float2(Cg[f][2], Cg[f][3]);
            }
        }
    }
    __syncthreads();
    if (kh == 0) {
        const float* m1 = (const float*)(sm + VO);
        const float* m2 = m1 + 8192;
        const float* m3 = m2 + 8192;
        #pragma unroll
        for (int g = 0; g < 2; g++) {
            int rr = wm * 32 + g * 16 + (l >> 2);
            float rd0 = 1.f / (sden[rr] + sden[128 + rr] + sden[256 + rr] + sden[384 + rr]);
            int rs = rr + 8;
            float rd1 = 1.f / (sden[rs] + sden[128 + rs] + sden[256 + rs] + sden[384 + rs]);
            float (*Cg)[4] = g ? C1 : C0;
            float* o0 = out + (size_t)(bN + t0 + rr) * FO_ + cb;
            float* o1 = out + (size_t)(bN + t0 + rs) * FO_ + cb;
            #pragma unroll
            for (int f = 0; f < 8; f++) {
                int i0 = rr * 64 + f * 8 + cb, i1 = rs * 64 + f * 8 + cb;
                float x0 = (Cg[f][0] + m1[i0] + m2[i0] + m3[i0]) * rd0;
                float x1 = (Cg[f][1] + m1[i0 + 1] + m2[i0 + 1] + m3[i0 + 1]) * rd0;
                float x2 = (Cg[f][2] + m1[i1] + m2[i1] + m3[i1]) * rd1;
                float x3 = (Cg[f][3] + m1[i1 + 1] + m2[i1 + 1] + m3[i1 + 1]) * rd1;
                x0 = (x0 > 0.f) ? x0 : 0.01f * x0;
                x1 = (x1 > 0.f) ? x1 : 0.01f * x1;
                x2 = (x2 > 0.f) ? x2 : 0.01f * x2;
                x3 = (x3 > 0.f) ? x3 : 0.01f * x3;
                *(float2*)o0 = make_float2(x0, x1);
                *(float2*)o1 = make_float2(x2, x3);
                o0 += 8; o1 += 8;
            }
        }
    }
}

// ---------------- launcher ----------------
extern "C" void kernel_launch(void* const* d_in, const int* in_sizes, int n_in,
                              void* d_out, int out_size) {
    const float* h   = (const float*)d_in[0];
    const float* ctx = (const float*)d_in[1];
    const int*   adj = (const int*)d_in[2];
    const float* Ws  = (const float*)d_in[3];
    const float* Wt  = (const float*)d_in[4];
    const float* a   = (const float*)d_in[5];
    float* out = (float*)d_out;

    cudaFuncSetAttribute(gat_prep, cudaFuncAttributeMaxDynamicSharedMemorySize, PREP_SMEM);
    cudaFuncSetAttribute(gat_main, cudaFuncAttributeMaxDynamicSharedMemorySize, SMEM_MAIN);

    gat_prep<<<384, 512, PREP_SMEM>>>(h, ctx, Ws, Wt, a);
    gat_main<<<B_ * (N_ / TM_), 512, SMEM_MAIN>>>(adj, out);
}

// round 13
// speedup vs baseline: 1.8327x; 1.1517x over previous
#include <cuda_runtime.h>
#include <cuda_fp16.h>
#include <cstdint>
#include <cstddef>

static constexpr int B_  = 4;
static constexpr int N_  = 4096;
static constexpr int F_  = 256;
static constexpr int FO_ = 64;
static constexpr int TM_ = 128;    // t rows per CTA

// main smem: EB1 16K | EB2 16K | V dbl-buf 2x32K (hi only) | sden 2K
// epilogue: merge partials occupy [0, 96K) (EB+V areas reused)
static constexpr int EB1O = 0;
static constexpr int EB2O = 16384;
static constexpr int VO   = 32768;
static constexpr int VBUF = 32768;
static constexpr int SDEN = 98304;
static constexpr int SMEM_MAIN = 100352;

// prep smem: WsHi 32K | WsLo 32K | a1 (64 floats)
static constexpr int PWSLO = 32768;
static constexpr int PA1   = 65536;
static constexpr int PREP_SMEM = 66048;

__device__ float g_EA1[B_ * N_];
__device__ float g_EA2[B_ * N_];
__device__ float g_EB1[B_ * N_];
__device__ float g_EB2[B_ * N_];
__device__ float g_pm1[256];
__device__ float g_pm2[256];
__device__ __half g_Vhi[(size_t)B_ * N_ * FO_];

__device__ __forceinline__ uint32_t smem_u32(const void* p) {
    uint32_t a;
    asm("{ .reg .u64 t; cvta.to.shared.u64 t, %1; cvt.u32.u64 %0, t; }" : "=r"(a) : "l"(p));
    return a;
}
// pack two fp32 -> bf16x2 by truncation: low <- a, high <- b
__device__ __forceinline__ uint32_t pack_hi(float a, float b) {
    uint32_t r;
    asm("prmt.b32 %0, %1, %2, 0x7632;" : "=r"(r)
        : "r"(__float_as_uint(a)), "r"(__float_as_uint(b)));
    return r;
}
// pack two fp32 -> bf16x2 (round-nearest): low <- a, high <- b
__device__ __forceinline__ uint32_t pack_rnb(float a, float b) {
    uint32_t r;
    asm("cvt.rn.bf16x2.f32 %0, %1, %2;" : "=r"(r) : "f"(b), "f"(a));
    return r;
}
// pack two fp32 -> f16x2 (round-nearest): low <- a, high <- b
__device__ __forceinline__ uint32_t pack_h2(float a, float b) {
    uint32_t r;
    asm("cvt.rn.f16x2.f32 %0, %1, %2;" : "=r"(r) : "f"(b), "f"(a));
    return r;
}
__device__ __forceinline__ float trunc_bf16(float a) {
    return __uint_as_float(__float_as_uint(a) & 0xFFFF0000u);
}
__device__ __forceinline__ void ldsm4t(uint32_t* r, uint32_t addr) {
    asm volatile("ldmatrix.sync.aligned.m8n8.x4.trans.shared.b16 {%0,%1,%2,%3}, [%4];"
        : "=r"(r[0]), "=r"(r[1]), "=r"(r[2]), "=r"(r[3]) : "r"(addr));
}
// fp16 mma (main)
__device__ __forceinline__ void mma16816h(float* c, uint32_t a0, uint32_t a1, uint32_t a2, uint32_t a3,
                                          uint32_t b0, uint32_t b1) {
    asm volatile("mma.sync.aligned.m16n8k16.row.col.f32.f16.f16.f32 "
        "{%0,%1,%2,%3}, {%4,%5,%6,%7}, {%8,%9}, {%0,%1,%2,%3};"
        : "+f"(c[0]), "+f"(c[1]), "+f"(c[2]), "+f"(c[3])
        : "r"(a0), "r"(a1), "r"(a2), "r"(a3), "r"(b0), "r"(b1));
}
// bf16 mma (prep)
__device__ __forceinline__ void mma16816b(float* c, uint32_t a0, uint32_t a1, uint32_t a2, uint32_t a3,
                                          uint32_t b0, uint32_t b1) {
    asm volatile("mma.sync.aligned.m16n8k16.row.col.f32.bf16.bf16.f32 "
        "{%0,%1,%2,%3}, {%4,%5,%6,%7}, {%8,%9}, {%0,%1,%2,%3};"
        : "+f"(c[0]), "+f"(c[1]), "+f"(c[2]), "+f"(c[3])
        : "r"(a0), "r"(a1), "r"(a2), "r"(a3), "r"(b0), "r"(b1));
}
__device__ __forceinline__ void cp16(uint32_t dst, const void* src) {
    asm volatile("cp.async.cg.shared.global [%0], [%1], 16;" :: "r"(dst), "l"(src) : "memory");
}
__device__ __forceinline__ void cp_commit() { asm volatile("cp.async.commit_group;" ::: "memory"); }
template <int NW>
__device__ __forceinline__ void cp_wait() { asm volatile("cp.async.wait_group %0;" :: "n"(NW) : "memory"); }
__device__ __forceinline__ void pref_l2(const void* p) {
    asm volatile("prefetch.global.L2 [%0];" :: "l"(p));
}

// ---------------- prep ----------------
// blocks 0..127 (256 thr): V = ctx@Ws via bf16 tensor-core split (3-term), fp16 store; sA->EA from fp32 accum
// blocks 128..383: EB (w2 inline) + per-block maxes
__global__ __launch_bounds__(256) void gat_prep(const float* __restrict__ h,
                                                const float* __restrict__ ctx,
                                                const float* __restrict__ Ws,
                                                const float* __restrict__ Wt,
                                                const float* __restrict__ a) {
    extern __shared__ char sm[];
    uint32_t smb = smem_u32(sm);
    int tid = threadIdx.x;
    int bx = blockIdx.x;
    if (bx < 128) {
        // stage Ws (256x64 fp32) as bf16 hi/lo tiles, swizzled rows of 128B
        {
            int f = tid;
            const float* wr = Ws + (size_t)f * FO_;
            #pragma unroll
            for (int ch = 0; ch < 8; ch++) {
                float4 v0 = *(const float4*)(wr + ch * 8);
                float4 v1 = *(const float4*)(wr + ch * 8 + 4);
                uint4 hh = make_uint4(pack_hi(v0.x, v0.y), pack_hi(v0.z, v0.w),
                                      pack_hi(v1.x, v1.y), pack_hi(v1.z, v1.w));
                uint4 ll = make_uint4(
                    pack_rnb(v0.x - trunc_bf16(v0.x), v0.y - trunc_bf16(v0.y)),
                    pack_rnb(v0.z - trunc_bf16(v0.z), v0.w - trunc_bf16(v0.w)),
                    pack_rnb(v1.x - trunc_bf16(v1.x), v1.y - trunc_bf16(v1.y)),
                    pack_rnb(v1.z - trunc_bf16(v1.z), v1.w - trunc_bf16(v1.w)));
                uint32_t off = (uint32_t)((f * 128 + ch * 16) ^ ((f & 7) << 4));
                *(uint4*)(sm + off) = hh;
                *(uint4*)(sm + PWSLO + off) = ll;
            }
            if (tid < 64) ((float*)(sm + PA1))[tid] = a[tid];
        }
        __syncthreads();

        int l = tid & 31, w = tid >> 5;       // 8 warps x 16 rows
        int row = bx * 128 + w * 16 + (l >> 2);
        int q2 = (l & 3) * 2;
        const float* cp0 = ctx + (size_t)row * F_ + q2;
        uint32_t swx = (uint32_t)((l & 7) << 4);
        uint32_t lbase = (uint32_t)((l & 15) * 128 + (l >> 4) * 16);

        float C[8][4];
        #pragma unroll
        for (int j = 0; j < 8; j++)
            #pragma unroll
            for (int i = 0; i < 4; i++) C[j][i] = 0.f;

        #pragma unroll 4
        for (int kc = 0; kc < 16; kc++) {
            int f0 = kc * 16;
            float2 x00 = *(const float2*)(cp0 + f0);
            float2 x10 = *(const float2*)(cp0 + 8 * F_ + f0);
            float2 x01 = *(const float2*)(cp0 + f0 + 8);
            float2 x11 = *(const float2*)(cp0 + 8 * F_ + f0 + 8);
            uint32_t ah0 = pack_hi(x00.x, x00.y), ah1 = pack_hi(x10.x, x10.y);
            uint32_t ah2 = pack_hi(x01.x, x01.y), ah3 = pack_hi(x11.x, x11.y);
            uint32_t al0 = pack_rnb(x00.x - trunc_bf16(x00.x), x00.y - trunc_bf16(x00.y));
            uint32_t al1 = pack_rnb(x10.x - trunc_bf16(x10.x), x10.y - trunc_bf16(x10.y));
            uint32_t al2 = pack_rnb(x01.x - trunc_bf16(x01.x), x01.y - trunc_bf16(x01.y));
            uint32_t al3 = pack_rnb(x11.x - trunc_bf16(x11.x), x11.y - trunc_bf16(x11.y));
            uint32_t fb = lbase + (uint32_t)(f0 * 128);
            #pragma unroll
            for (int g = 0; g < 4; g++) {
                uint32_t off = (fb + (uint32_t)(g * 32)) ^ swx;
                uint32_t bh[4], bl[4];
                ldsm4t(bh, smb + off);
                ldsm4t(bl, smb + PWSLO + off);
                mma16816b(C[2 * g],     ah0, ah1, ah2, ah3, bh[0], bh[1]);
                mma16816b(C[2 * g + 1], ah0, ah1, ah2, ah3, bh[2], bh[3]);
                mma16816b(C[2 * g],     al0, al1, al2, al3, bh[0], bh[1]);
                mma16816b(C[2 * g + 1], al0, al1, al2, al3, bh[2], bh[3]);
                mma16816b(C[2 * g],     ah0, ah1, ah2, ah3, bl[0], bl[1]);
                mma16816b(C[2 * g + 1], ah0, ah1, ah2, ah3, bl[2], bl[3]);
            }
        }

        // store V as fp16; compute sA from fp32 accum
        __half* vo = g_Vhi + (size_t)row * FO_;
        const float* a1s = (const float*)(sm + PA1);
        float s0 = 0.f, s1 = 0.f;
        #pragma unroll
        for (int j = 0; j < 8; j++) {
            int nb = (j >> 1) * 16 + (j & 1) * 8 + q2;
            *(uint32_t*)(vo + nb)           = pack_h2(C[j][0], C[j][1]);
            *(uint32_t*)(vo + 8 * FO_ + nb) = pack_h2(C[j][2], C[j][3]);
            float2 av = *(const float2*)&a1s[nb];
            s0 += C[j][0] * av.x + C[j][1] * av.y;
            s1 += C[j][2] * av.x + C[j][3] * av.y;
        }
        s0 += __shfl_xor_sync(0xffffffffu, s0, 1);
        s0 += __shfl_xor_sync(0xffffffffu, s0, 2);
        s1 += __shfl_xor_sync(0xffffffffu, s1, 1);
        s1 += __shfl_xor_sync(0xffffffffu, s1, 2);
        if ((l & 3) == 0) {
            g_EA1[row] = __expf(s0);
            g_EA2[row] = __expf(0.2f * s0);
            g_EA1[row + 8] = __expf(s1);
            g_EA2[row + 8] = __expf(0.2f * s1);
        }
    } else {
        // EB role: 64 rows/block, w2 inline, per-block maxes
        float* w2s = (float*)sm;  // 256 floats
        {
            float acc = 0.f;
            const float* wr = Wt + (size_t)tid * FO_;
            #pragma unroll 8
            for (int o = 0; o < FO_; o++) acc += wr[o] * a[FO_ + o];
            w2s[tid] = acc;
        }
        __syncthreads();
        int lane = tid & 31, w = tid >> 5;   // 8 warps
        int rb = (bx - 128) * 64;
        const float4* wp = (const float4*)w2s;
        float4 w0 = wp[lane], w1 = wp[lane + 32];
        float m1 = 0.f, m2 = 0.f;
        #pragma unroll
        for (int it = 0; it < 8; it++) {
            int sg = rb + it * 8 + w;
            const float4* hp = (const float4*)(h + (size_t)sg * F_);
            float4 x0 = hp[lane], x1 = hp[lane + 32];
            float d = x0.x * w0.x + x0.y * w0.y + x0.z * w0.z + x0.w * w0.w
                    + x1.x * w1.x + x1.y * w1.y + x1.z * w1.z + x1.w * w1.w;
            #pragma unroll
            for (int off = 16; off > 0; off >>= 1) d += __shfl_xor_sync(0xffffffffu, d, off);
            if (lane == 0) {
                float e1 = __expf(d), e2 = __expf(0.2f * d);
                g_EB1[sg] = e1;
                g_EB2[sg] = e2;
                m1 = fmaxf(m1, e1);
                m2 = fmaxf(m2, e2);
            }
        }
        __syncthreads();
        float* wmx = (float*)sm;  // reuse
        if (lane == 0) { wmx[w] = m1; wmx[8 + w] = m2; }
        __syncthreads();
        if (tid < 2) {
            const float* src = wmx + tid * 8;
            float m = src[0];
            #pragma unroll
            for (int i = 1; i < 8; i++) m = fmaxf(m, src[i]);
            if (tid == 0) g_pm1[bx - 128] = m;
            else          g_pm2[bx - 128] = m;
        }
    }
}

// ---------------- main: fp16 P single-term x fp16 V single-term ----------------
__global__ __launch_bounds__(512, 1)
void gat_main(const int* __restrict__ adj, float* __restrict__ out) {
    extern __shared__ char sm[];
    uint32_t smb = smem_u32(sm);
    float* EB1s = (float*)(sm + EB1O);
    float* EB2s = (float*)(sm + EB2O);
    float* sden = (float*)(sm + SDEN);   // [4][128]

    int tid = threadIdx.x;
    int l = tid & 31, wid = tid >> 5;
    int cta = blockIdx.x;
    int b = cta >> 5;
    int t0 = (cta & 31) * TM_;
    int bN = b * N_;
    int wm = wid & 3;
    int kh = wid >> 2;

    {
        const float4* s1 = (const float4*)(g_EB1 + bN);
        const float4* s2 = (const float4*)(g_EB2 + bN);
        float4* d1 = (float4*)EB1s;
        float4* d2 = (float4*)EB2s;
        d1[tid] = s1[tid]; d1[tid + 512] = s1[tid + 512];
        d2[tid] = s2[tid]; d2[tid + 512] = s2[tid + 512];
        if (tid < 64) {
            sden[tid]      = g_pm1[b * 64 + tid];
            sden[64 + tid] = g_pm2[b * 64 + tid];
        }
    }
    __syncthreads();
    float mB1 = sden[0], mB2 = sden[64];
    #pragma unroll
    for (int i = 1; i < 64; i++) {
        mB1 = fmaxf(mB1, sden[i]);
        mB2 = fmaxf(mB2, sden[64 + i]);
    }

    int r0 = wm * 32 + (l >> 2);
    int cb = (l & 3) * 2;
    float ea1[4], ea2[4];
    #pragma unroll
    for (int p = 0; p < 4; p++) {
        float e1 = g_EA1[bN + t0 + r0 + p * 8];
        float e2 = g_EA2[bN + t0 + r0 + p * 8];
        float M = fmaxf(e1 * mB1, e2 * mB2);
        uint32_t eb = (__float_as_uint(M) >> 23) & 0xFFu;
        float s = __uint_as_float((267u - eb) << 23);   // scaled bound in [2^13, 2^14)
        ea1[p] = e1 * s;
        ea2[p] = e2 * s;
    }
    const int* adjB = adj + (size_t)(bN + t0 + r0) * N_;

    // cp.async V mapping (fp16 rows of 128B)
    int vr = tid >> 3, vc = tid & 7;
    uint32_t vdsw = (uint32_t)((vr * 128 + vc * 16) ^ ((vr & 7) << 4));
    const char* vsh = (const char*)(g_Vhi + ((size_t)bN + vr) * FO_ + vc * 8);

    uint32_t lb = (uint32_t)((kh * 64 + (l & 15)) * 128 + (l >> 4) * 16);
    uint32_t swx = (uint32_t)((l & 7) << 4);

    // prologue: V super-block 0 (256 rows, hi only)
    {
        uint32_t d = smb + VO + vdsw;
        #pragma unroll
        for (int rho = 0; rho < 4; rho++) cp16(d + rho * 8192, vsh + rho * 8192);
        cp_commit();
    }
    int2 ajn[8];
    {
        int c0 = kh * 64 + cb;
        #pragma unroll
        for (int p = 0; p < 4; p++) {
            ajn[2 * p]     = *(const int2*)(adjB + (size_t)p * 8 * N_ + c0);
            ajn[2 * p + 1] = *(const int2*)(adjB + (size_t)p * 8 * N_ + c0 + 8);
        }
    }

    float C0[8][4], C1[8][4];
    #pragma unroll
    for (int f = 0; f < 8; f++)
        #pragma unroll
        for (int i = 0; i < 4; i++) { C0[f][i] = 0.f; C1[f][i] = 0.f; }
    float dden[4] = {0.f, 0.f, 0.f, 0.f};

    for (int j = 0; j < 16; j++) {
        if (j < 15) {
            uint32_t d = smb + VO + (uint32_t)(((j + 1) & 1) * VBUF) + vdsw;
            const char* sh = vsh + (size_t)(j + 1) * 32768;
            #pragma unroll
            for (int rho = 0; rho < 4; rho++) cp16(d + rho * 8192, sh + rho * 8192);
            cp_commit();
            if ((l & 3) == 0) {
                int sn2 = (j + 1) * 256 + kh * 64;
                #pragma unroll
                for (int p = 0; p < 4; p++) {
                    const char* pf = (const char*)(adjB + (size_t)p * 8 * N_ + sn2);
                    pref_l2(pf);
                    pref_l2(pf + 128);
                }
            }
            cp_wait<1>();
        } else {
            cp_wait<0>();
        }
        __syncthreads();

        uint32_t vbhi = smb + VO + (uint32_t)((j & 1) * VBUF);
        int sj = j * 256 + kh * 64;

        #pragma unroll
        for (int kk = 0; kk < 4; kk++) {
            int c0 = sj + kk * 16 + cb;
            int2 aj[8];
            #pragma unroll
            for (int q = 0; q < 8; q++) aj[q] = ajn[q];
            {
                int cn = (kk < 3) ? (c0 + 16) : ((j < 15) ? (c0 + 208) : c0);
                #pragma unroll
                for (int p = 0; p < 4; p++) {
                    ajn[2 * p]     = *(const int2*)(adjB + (size_t)p * 8 * N_ + cn);
                    ajn[2 * p + 1] = *(const int2*)(adjB + (size_t)p * 8 * N_ + cn + 8);
                }
            }
            float2 e1a = *(const float2*)&EB1s[c0];
            float2 e1b = *(const float2*)&EB1s[c0 + 8];
            float2 e2a = *(const float2*)&EB2s[c0];
            float2 e2b = *(const float2*)&EB2s[c0 + 8];

            uint32_t hA[4], hB[4];
            #pragma unroll
            for (int p = 0; p < 4; p++) {
                int2 A0 = aj[2 * p], A1 = aj[2 * p + 1];
                float x0, x1, x2, x3;
                x0 = fmaxf(ea1[p] * e1a.x, ea2[p] * e2a.x); x0 = (A0.x > 0) ? x0 : 0.f;
                x1 = fmaxf(ea1[p] * e1a.y, ea2[p] * e2a.y); x1 = (A0.y > 0) ? x1 : 0.f;
                x2 = fmaxf(ea1[p] * e1b.x, ea2[p] * e2b.x); x2 = (A1.x > 0) ? x2 : 0.f;
                x3 = fmaxf(ea1[p] * e1b.y, ea2[p] * e2b.y); x3 = (A1.y > 0) ? x3 : 0.f;
                dden[p] += (x0 + x1) + (x2 + x3);
                hA[p] = pack_h2(x0, x1);
                hB[p] = pack_h2(x2, x3);
            }
            uint32_t ob = lb + (uint32_t)(kk * 2048);
            #pragma unroll
            for (int ng = 0; ng < 4; ng++) {
                uint32_t off = (ob + (uint32_t)(ng * 32)) ^ swx;
                uint32_t bh[4];
                ldsm4t(bh, vbhi + off);
                mma16816h(C0[2 * ng],     hA[0], hA[1], hB[0], hB[1], bh[0], bh[1]);
                mma16816h(C1[2 * ng],     hA[2], hA[3], hB[2], hB[3], bh[0], bh[1]);
                mma16816h(C0[2 * ng + 1], hA[0], hA[1], hB[0], hB[1], bh[2], bh[3]);
                mma16816h(C1[2 * ng + 1], hA[2], hA[3], hB[2], hB[3], bh[2], bh[3]);
            }
        }
        __syncthreads();
    }

    // ---- epilogue ----
    #pragma unroll
    for (int p = 0; p < 4; p++) {
        dden[p] += __shfl_xor_sync(0xffffffffu, dden[p], 1);
        dden[p] += __shfl_xor_sync(0xffffffffu, dden[p], 2);
    }
    if ((l & 3) == 0) {
        #pragma unroll
        for (int p = 0; p < 4; p++) sden[kh * 128 + r0 + p * 8] = dden[p];
    }
    // kh=1..3 dump partials at smem offset 0 (EB/V areas dead now): [kh-1][128][64] floats
    if (kh) {
        float* mb = (float*)sm + (size_t)(kh - 1) * 8192;
        #pragma unroll
        for (int g = 0; g < 2; g++) {
            int rr = wm * 32 + g * 16 + (l >> 2);
            float (*Cg)[4] = g ? C1 : C0;
            #pragma unroll
            for (int f = 0; f < 8; f++) {
                *(float2*)&mb[rr * 64 + f * 8 + cb]       = make_float2(Cg[f][0], Cg[f][1]);
                *(float2*)&mb[(rr + 8) * 64 + f * 8 + cb] = make_float2(Cg[f][2], Cg[f][3]);
            }
        }
    }
    __syncthreads();
    if (kh == 0) {
        const float* m1 = (const float*)sm;
        const float* m2 = m1 + 8192;
        const float* m3 = m2 + 8192;
        #pragma unroll
        for (int g = 0; g < 2; g++) {
            int rr = wm * 32 + g * 16 + (l >> 2);
            float rd0 = 1.f / (sden[rr] + sden[128 + rr] + sden[256 + rr] + sden[384 + rr]);
            int rs = rr + 8;
            float rd1 = 1.f / (sden[rs] + sden[128 + rs] + sden[256 + rs] + sden[384 + rs]);
            float (*Cg)[4] = g ? C1 : C0;
            float* o0 = out + (size_t)(bN + t0 + rr) * FO_ + cb;
            float* o1 = out + (size_t)(bN + t0 + rs) * FO_ + cb;
            #pragma unroll
            for (int f = 0; f < 8; f++) {
                int i0 = rr * 64 + f * 8 + cb, i1 = rs * 64 + f * 8 + cb;
                float x0 = (Cg[f][0] + m1[i0] + m2[i0] + m3[i0]) * rd0;
                float x1 = (Cg[f][1] + m1[i0 + 1] + m2[i0 + 1] + m3[i0 + 1]) * rd0;
                float x2 = (Cg[f][2] + m1[i1] + m2[i1] + m3[i1]) * rd1;
                float x3 = (Cg[f][3] + m1[i1 + 1] + m2[i1 + 1] + m3[i1 + 1]) * rd1;
                x0 = (x0 > 0.f) ? x0 : 0.01f * x0;
                x1 = (x1 > 0.f) ? x1 : 0.01f * x1;
                x2 = (x2 > 0.f) ? x2 : 0.01f * x2;
                x3 = (x3 > 0.f) ? x3 : 0.01f * x3;
                *(float2*)o0 = make_float2(x0, x1);
                *(float2*)o1 = make_float2(x2, x3);
                o0 += 8; o1 += 8;
            }
        }
    }
}

// ---------------- launcher ----------------
extern "C" void kernel_launch(void* const* d_in, const int* in_sizes, int n_in,
                              void* d_out, int out_size) {
    const float* h   = (const float*)d_in[0];
    const float* ctx = (const float*)d_in[1];
    const int*   adj = (const int*)d_in[2];
    const float* Ws  = (const float*)d_in[3];
    const float* Wt  = (const float*)d_in[4];
    const float* a   = (const float*)d_in[5];
    float* out = (float*)d_out;

    cudaFuncSetAttribute(gat_prep, cudaFuncAttributeMaxDynamicSharedMemorySize, PREP_SMEM);
    cudaFuncSetAttribute(gat_main, cudaFuncAttributeMaxDynamicSharedMemorySize, SMEM_MAIN);

    gat_prep<<<384, 256, PREP_SMEM>>>(h, ctx, Ws, Wt, a);
    gat_main<<<B_ * (N_ / TM_), 512, SMEM_MAIN>>>(adj, out);
}